// round 10
// baseline (speedup 1.0000x reference)
#include <cuda_runtime.h>

// QuanvLayer closed form:
//   z_i = cos(w_i) * cos(x_i)   (patch elements p00,p01,p10,p11)
//   out[q=0] = z1*z2*z3 ; out[q=1] = z0*z1 ; out[q=2] = z0*z1*z2 ; out[q=3] = z0*z1*z2*z3
//
// x: (128, 3, 128, 128) f32 ; weights: (1,4) f32 ; out: (128, 12, 64, 64) f32
//
// R10: UNIFORM dual-chunk. 768 blocks x 256 = 196608 threads; every thread
// handles chunks t and t+196608 (= bc+192, constant offset). All 8 LDG.128
// front-batched (MLP=8 for EVERY warp, vs only 30% of warps in R7), no
// heavy/light predicate, single wave.

#define B_ 128
#define C_ 3
#define H_ 128
#define W_ 128
#define HH 64
#define WH 64

#define NBLOCKS 768
#define NTHREADS 256
// chunk stride 196608 = 192*1024 -> bc += 192
#define XOFF2 ((size_t)192 * H_ * W_)            // input float offset, chunk B
#define OOFF2 ((size_t)4 * 192 * HH * WH)        // output float offset, chunk B

__device__ __forceinline__ void quanv_patch4(
    const float4& t0, const float4& t1, const float4& b0, const float4& b1,
    float cw0, float cw1, float cw2, float cw3, float* __restrict__ o)
{
    float top[8] = {t0.x, t0.y, t0.z, t0.w, t1.x, t1.y, t1.z, t1.w};
    float bot[8] = {b0.x, b0.y, b0.z, b0.w, b1.x, b1.y, b1.z, b1.w};
    float o0[4], o1[4], o2[4], o3[4];
    #pragma unroll
    for (int p = 0; p < 4; p++) {
        float z0 = cw0 * __cosf(top[2*p]);
        float z1 = cw1 * __cosf(top[2*p + 1]);
        float z2 = cw2 * __cosf(bot[2*p]);
        float z3 = cw3 * __cosf(bot[2*p + 1]);
        float q1 = z0 * z1;
        float q2 = q1 * z2;
        float q3 = q2 * z3;
        float q0 = z1 * z2 * z3;
        o0[p] = q0; o1[p] = q1; o2[p] = q2; o3[p] = q3;
    }
    *reinterpret_cast<float4*>(o)           = make_float4(o0[0], o0[1], o0[2], o0[3]);
    *reinterpret_cast<float4*>(o + 1*HH*WH) = make_float4(o1[0], o1[1], o1[2], o1[3]);
    *reinterpret_cast<float4*>(o + 2*HH*WH) = make_float4(o2[0], o2[1], o2[2], o2[3]);
    *reinterpret_cast<float4*>(o + 3*HH*WH) = make_float4(o3[0], o3[1], o3[2], o3[3]);
}

__global__ void __launch_bounds__(NTHREADS)
quanv_kernel(const float* __restrict__ x,
             const float* __restrict__ w,
             float* __restrict__ out)
{
    const float cw0 = __cosf(__ldg(w + 0));
    const float cw1 = __cosf(__ldg(w + 1));
    const float cw2 = __cosf(__ldg(w + 2));
    const float cw3 = __cosf(__ldg(w + 3));

    int tid = blockIdx.x * NTHREADS + threadIdx.x;   // [0, 196608)

    // tid = (bc*HH + h2)*16 + w8 ; w8 covers 4 patches (8 input cols)
    int w8 = tid & 15;
    int h2 = (tid >> 4) & (HH - 1);
    int bc = tid >> 10;                              // [0, 192)

    const float* rowA = x + ((size_t)bc * H_ + 2 * h2) * W_ + 8 * w8;
    const float* rowB = rowA + XOFF2;

    // 8 front-batched LDG.128 — uniform MLP=8 for every thread
    const float4 At0 = *reinterpret_cast<const float4*>(rowA);
    const float4 At1 = *reinterpret_cast<const float4*>(rowA + 4);
    const float4 Ab0 = *reinterpret_cast<const float4*>(rowA + W_);
    const float4 Ab1 = *reinterpret_cast<const float4*>(rowA + W_ + 4);
    const float4 Bt0 = *reinterpret_cast<const float4*>(rowB);
    const float4 Bt1 = *reinterpret_cast<const float4*>(rowB + 4);
    const float4 Bb0 = *reinterpret_cast<const float4*>(rowB + W_);
    const float4 Bb1 = *reinterpret_cast<const float4*>(rowB + W_ + 4);

    float* oA = out + (((size_t)4 * bc) * HH + h2) * WH + 4 * w8;
    quanv_patch4(At0, At1, Ab0, Ab1, cw0, cw1, cw2, cw3, oA);
    quanv_patch4(Bt0, Bt1, Bb0, Bb1, cw0, cw1, cw2, cw3, oA + OOFF2);
}

extern "C" void kernel_launch(void* const* d_in, const int* in_sizes, int n_in,
                              void* d_out, int out_size)
{
    const float* x = (const float*)d_in[0];
    const float* w = (const float*)d_in[1];
    if (n_in >= 2 && in_sizes[0] == 4) {
        x = (const float*)d_in[1];
        w = (const float*)d_in[0];
    }
    float* out = (float*)d_out;

    quanv_kernel<<<NBLOCKS, NTHREADS>>>(x, w, out);
}

// round 11
// speedup vs baseline: 1.1185x; 1.1185x over previous
#include <cuda_runtime.h>

// QuanvLayer closed form:
//   z_i = cos(w_i) * cos(x_i)   (patch elements p00,p01,p10,p11)
//   out[q=0] = z1*z2*z3 ; out[q=1] = z0*z1 ; out[q=2] = z0*z1*z2 ; out[q=3] = z0*z1*z2*z3
//
// x: (128, 3, 128, 128) f32 ; weights: (1,4) f32 ; out: (128, 12, 64, 64) f32
//
// R11 = R7 resubmitted unchanged (best measured: 9.376us) for reproducibility.
// Structure: persistent 1184x256 (8 blocks/SM full residency) + front-batched
// second chunk. stride 303104 = 296*1024, so chunk B = chunk A with bc+=296
// (same h2,w8): B's loads are A's pointer + constant offset. Heavy threads
// (bc<88) issue all 8 LDG.128 before any compute.

#define B_ 128
#define C_ 3
#define H_ 128
#define W_ 128
#define HH 64
#define WH 64

#define NBLOCKS 1184
#define NTHREADS 256
#define XOFF2 (296 * H_ * W_)                    // second-chunk input offset (floats)
#define OOFF2 ((size_t)4 * 296 * HH * WH)        // second-chunk output offset (floats)

__device__ __forceinline__ void quanv_patch4(
    const float4& t0, const float4& t1, const float4& b0, const float4& b1,
    float cw0, float cw1, float cw2, float cw3, float* __restrict__ o)
{
    float top[8] = {t0.x, t0.y, t0.z, t0.w, t1.x, t1.y, t1.z, t1.w};
    float bot[8] = {b0.x, b0.y, b0.z, b0.w, b1.x, b1.y, b1.z, b1.w};
    float o0[4], o1[4], o2[4], o3[4];
    #pragma unroll
    for (int p = 0; p < 4; p++) {
        float z0 = cw0 * __cosf(top[2*p]);
        float z1 = cw1 * __cosf(top[2*p + 1]);
        float z2 = cw2 * __cosf(bot[2*p]);
        float z3 = cw3 * __cosf(bot[2*p + 1]);
        float q1 = z0 * z1;
        float q2 = q1 * z2;
        float q3 = q2 * z3;
        float q0 = z1 * z2 * z3;
        o0[p] = q0; o1[p] = q1; o2[p] = q2; o3[p] = q3;
    }
    *reinterpret_cast<float4*>(o)           = make_float4(o0[0], o0[1], o0[2], o0[3]);
    *reinterpret_cast<float4*>(o + 1*HH*WH) = make_float4(o1[0], o1[1], o1[2], o1[3]);
    *reinterpret_cast<float4*>(o + 2*HH*WH) = make_float4(o2[0], o2[1], o2[2], o2[3]);
    *reinterpret_cast<float4*>(o + 3*HH*WH) = make_float4(o3[0], o3[1], o3[2], o3[3]);
}

__global__ void __launch_bounds__(NTHREADS)
quanv_kernel(const float* __restrict__ x,
             const float* __restrict__ w,
             float* __restrict__ out)
{
    const float cw0 = __cosf(__ldg(w + 0));
    const float cw1 = __cosf(__ldg(w + 1));
    const float cw2 = __cosf(__ldg(w + 2));
    const float cw3 = __cosf(__ldg(w + 3));

    int tid = blockIdx.x * NTHREADS + threadIdx.x;

    // tid = (bc*HH + h2)*16 + w8 ; w8 covers 4 patches (8 input cols)
    int w8 = tid & 15;
    int h2 = (tid >> 4) & (HH - 1);
    int bc = tid >> 10;                          // [0, 296)
    bool heavy = (bc < 88);                      // second chunk exists

    const float* rowA = x + ((size_t)bc * H_ + 2 * h2) * W_ + 8 * w8;
    const float4 At0 = *reinterpret_cast<const float4*>(rowA);
    const float4 At1 = *reinterpret_cast<const float4*>(rowA + 4);
    const float4 Ab0 = *reinterpret_cast<const float4*>(rowA + W_);
    const float4 Ab1 = *reinterpret_cast<const float4*>(rowA + W_ + 4);

    float4 Bt0, Bt1, Bb0, Bb1;
    const float* rowB = rowA + XOFF2;
    if (heavy) {
        Bt0 = *reinterpret_cast<const float4*>(rowB);
        Bt1 = *reinterpret_cast<const float4*>(rowB + 4);
        Bb0 = *reinterpret_cast<const float4*>(rowB + W_);
        Bb1 = *reinterpret_cast<const float4*>(rowB + W_ + 4);
    }

    float* oA = out + (((size_t)4 * bc) * HH + h2) * WH + 4 * w8;
    quanv_patch4(At0, At1, Ab0, Ab1, cw0, cw1, cw2, cw3, oA);

    if (heavy) {
        quanv_patch4(Bt0, Bt1, Bb0, Bb1, cw0, cw1, cw2, cw3, oA + OOFF2);
    }
}

extern "C" void kernel_launch(void* const* d_in, const int* in_sizes, int n_in,
                              void* d_out, int out_size)
{
    const float* x = (const float*)d_in[0];
    const float* w = (const float*)d_in[1];
    if (n_in >= 2 && in_sizes[0] == 4) {
        x = (const float*)d_in[1];
        w = (const float*)d_in[0];
    }
    float* out = (float*)d_out;

    quanv_kernel<<<NBLOCKS, NTHREADS>>>(x, w, out);
}